// round 1
// baseline (speedup 1.0000x reference)
#include <cuda_runtime.h>

#define B_ 64
#define N_ 1024
#define F_ 128
#define H_ 256

// Scratch (allocation-free rule: __device__ globals)
__device__ float g_T1[B_ * N_ * F_];     // adj @ embs          [B,N,F]
__device__ float g_hid1[B_ * N_ * H_];   // relu(T1@W0 + b0)    [B,N,H]
__device__ float g_T2[B_ * N_ * H_];     // hid1 @ W1           [B,N,H]
__device__ float g_hid2[B_ * N_ * H_];   // relu(adj@T2 + b1)   [B,N,H]

// Classic 128x128x8 double-buffered SGEMM, 256 threads, 8x8 microtile
// (4x4 quadrant split for conflict-free LDS.128). Row-major A[M,K], B[K,Nn],
// C[M,Nn] with batch strides (stride 0 => shared operand). Optional bias+relu.
__global__ __launch_bounds__(256, 2)
void sgemm128(const float* __restrict__ A, const float* __restrict__ Bm,
              float* __restrict__ C, int M, int Nn, int K,
              long sA, long sB, long sC,
              const float* __restrict__ bias, int relu)
{
    const int bz = blockIdx.z;
    A  += (size_t)bz * sA;
    Bm += (size_t)bz * sB;
    C  += (size_t)bz * sC;

    __shared__ float As[2][8][128];
    __shared__ float Bs[2][8][128];

    const int tid = threadIdx.x;
    const int m0 = blockIdx.y * 128;
    const int n0 = blockIdx.x * 128;

    // Global load mapping: A tile 128x8 (transposed into smem), B tile 8x128
    const int a_row = tid >> 1;
    const int a_col = (tid & 1) * 4;
    const int b_row = tid >> 5;
    const int b_col = (tid & 31) * 4;

    const float* Ap = A  + (size_t)(m0 + a_row) * K + a_col;
    const float* Bp = Bm + (size_t)b_row * Nn + n0 + b_col;

    float acc[8][8];
#pragma unroll
    for (int i = 0; i < 8; i++)
#pragma unroll
        for (int j = 0; j < 8; j++) acc[i][j] = 0.f;

    // prologue: stage k-tile 0
    {
        float4 av = *(const float4*)Ap;
        float4 bv = *(const float4*)Bp;
        As[0][a_col + 0][a_row] = av.x;
        As[0][a_col + 1][a_row] = av.y;
        As[0][a_col + 2][a_row] = av.z;
        As[0][a_col + 3][a_row] = av.w;
        *(float4*)&Bs[0][b_row][b_col] = bv;
    }
    __syncthreads();

    const int tx = tid & 15;
    const int ty = tid >> 4;

    const int nk = K >> 3;
    int buf = 0;
    for (int t = 0; t < nk; t++) {
        float4 av, bv;
        const bool nxt = (t + 1 < nk);
        if (nxt) {
            av = *(const float4*)(Ap + (t + 1) * 8);
            bv = *(const float4*)(Bp + (size_t)(t + 1) * 8 * Nn);
        }
#pragma unroll
        for (int k = 0; k < 8; k++) {
            float a[8], bb[8];
            *(float4*)&a[0]  = *(const float4*)&As[buf][k][ty * 4];
            *(float4*)&a[4]  = *(const float4*)&As[buf][k][64 + ty * 4];
            *(float4*)&bb[0] = *(const float4*)&Bs[buf][k][tx * 4];
            *(float4*)&bb[4] = *(const float4*)&Bs[buf][k][64 + tx * 4];
#pragma unroll
            for (int i = 0; i < 8; i++)
#pragma unroll
                for (int j = 0; j < 8; j++)
                    acc[i][j] = fmaf(a[i], bb[j], acc[i][j]);
        }
        const int nb = buf ^ 1;
        if (nxt) {
            As[nb][a_col + 0][a_row] = av.x;
            As[nb][a_col + 1][a_row] = av.y;
            As[nb][a_col + 2][a_row] = av.z;
            As[nb][a_col + 3][a_row] = av.w;
            *(float4*)&Bs[nb][b_row][b_col] = bv;
        }
        __syncthreads();
        buf = nb;
    }

    // epilogue
#pragma unroll
    for (int i = 0; i < 8; i++) {
        const int m = m0 + ((i < 4) ? (ty * 4 + i) : (64 + ty * 4 + i - 4));
#pragma unroll
        for (int jh = 0; jh < 2; jh++) {
            const int n = n0 + jh * 64 + tx * 4;
            float4 v;
            v.x = acc[i][jh * 4 + 0];
            v.y = acc[i][jh * 4 + 1];
            v.z = acc[i][jh * 4 + 2];
            v.w = acc[i][jh * 4 + 3];
            if (bias) {
                v.x += bias[n + 0]; v.y += bias[n + 1];
                v.z += bias[n + 2]; v.w += bias[n + 3];
            }
            if (relu) {
                v.x = fmaxf(v.x, 0.f); v.y = fmaxf(v.y, 0.f);
                v.z = fmaxf(v.z, 0.f); v.w = fmaxf(v.w, 0.f);
            }
            *(float4*)&C[(size_t)m * Nn + n] = v;
        }
    }
}

// Layer-2 + linear head, sliced to node 0 only:
// r[b,:]  = adj[b,0,:] @ hid2[b]              (N dot per h)
// s[b,:]  = relu(r @ W2 + b2)
// out[b,:] = s @ Wl + bl
__global__ void tail_kernel(const float* __restrict__ adj,
                            const float* __restrict__ hid2,
                            const float* __restrict__ W2,
                            const float* __restrict__ b2,
                            const float* __restrict__ Wl,
                            const float* __restrict__ bl,
                            float* __restrict__ out)
{
    const int b = blockIdx.x;
    const int t = threadIdx.x;  // 256 threads
    __shared__ float arow[N_];
    __shared__ float rs[H_];
    __shared__ float ss[H_];

    const float* ar = adj + (size_t)b * N_ * N_;  // row 0 of graph b
    for (int n = t; n < N_; n += 256) arow[n] = ar[n];
    __syncthreads();

    const float* h2 = hid2 + (size_t)b * N_ * H_;
    float acc = 0.f;
#pragma unroll 4
    for (int n = 0; n < N_; n++)
        acc = fmaf(arow[n], h2[(size_t)n * H_ + t], acc);
    rs[t] = acc;
    __syncthreads();

    float a2 = b2[t];
#pragma unroll 4
    for (int k = 0; k < H_; k++)
        a2 = fmaf(rs[k], W2[k * H_ + t], a2);
    ss[t] = fmaxf(a2, 0.f);
    __syncthreads();

    if (t < F_) {
        float a3 = bl[t];
#pragma unroll 4
        for (int k = 0; k < H_; k++)
            a3 = fmaf(ss[k], Wl[k * F_ + t], a3);
        out[b * F_ + t] = a3;
    }
}

extern "C" void kernel_launch(void* const* d_in, const int* in_sizes, int n_in,
                              void* d_out, int out_size)
{
    const float* embs = (const float*)d_in[0];
    const float* adj  = (const float*)d_in[1];
    const float* W0   = (const float*)d_in[2];
    const float* b0   = (const float*)d_in[3];
    const float* W1   = (const float*)d_in[4];
    const float* b1   = (const float*)d_in[5];
    const float* W2   = (const float*)d_in[6];
    const float* b2   = (const float*)d_in[7];
    const float* Wl   = (const float*)d_in[8];
    const float* bl   = (const float*)d_in[9];
    float* out = (float*)d_out;

    float *T1, *hid1, *T2, *hid2;
    cudaGetSymbolAddress((void**)&T1, g_T1);
    cudaGetSymbolAddress((void**)&hid1, g_hid1);
    cudaGetSymbolAddress((void**)&T2, g_T2);
    cudaGetSymbolAddress((void**)&hid2, g_hid2);

    // L0 part A: T1 = adj @ embs   (per graph: [1024x1024]@[1024x128])
    sgemm128<<<dim3(1, 8, 64), 256>>>(adj, embs, T1, N_, F_, N_,
                                      (long)N_ * N_, (long)N_ * F_, (long)N_ * F_,
                                      nullptr, 0);
    // L0 part B: hid1 = relu(T1 @ W0 + b0)   ([65536x128]@[128x256])
    sgemm128<<<dim3(2, 512, 1), 256>>>(T1, W0, hid1, B_ * N_, H_, F_,
                                       0, 0, 0, b0, 1);
    // L1 part A: T2 = hid1 @ W1   ([65536x256]@[256x256])
    sgemm128<<<dim3(2, 512, 1), 256>>>(hid1, W1, T2, B_ * N_, H_, H_,
                                       0, 0, 0, nullptr, 0);
    // L1 part B: hid2 = relu(adj @ T2 + b1)  (per graph: [1024x1024]@[1024x256])
    sgemm128<<<dim3(2, 8, 64), 256>>>(adj, T2, hid2, N_, H_, N_,
                                      (long)N_ * N_, (long)N_ * H_, (long)N_ * H_,
                                      b1, 1);
    // L2 (node-0 slice only) + linear head
    tail_kernel<<<B_, 256>>>(adj, hid2, W2, b2, Wl, bl, out);
}